// round 8
// baseline (speedup 1.0000x reference)
#include <cuda_runtime.h>
#include <cuda_fp16.h>
#include <cstdint>

// GCN layer on GB300. CSR build -> nh fp16 convert -> ONE fused persistent
// kernel (aggregate -> GEMM1 -> GEMM2, fp16 HMMA m16n8k16, W held as
// register A-fragments, x/h tiles in smem) -> eh passthrough.
// Trick: compute D^T = W^T @ X^T so W is the mma A operand and its
// fragments are loaded once per block and reused across all m-tiles.

#define NN 100000
#define EE 1600000
#define DD 128
#define MTILES 6250        // 100000/16
#define NBLK 391           // ceil(NN/256)
#define GRID_FUSED 296     // 2 blocks/SM * 148 SMs

__device__ __align__(128) int    g_cnt[NN];
__device__ __align__(128) int    g_off[NN];
__device__ __align__(128) int    g_cur[NN];
__device__ __align__(128) int    g_bsum[512];
__device__ __align__(128) int    g_bscan[512];
__device__ __align__(128) int    g_esrc[EE];
__device__ __align__(128) float  g_dis[NN];
__device__ __align__(128) __half2 g_nhh[(size_t)NN * 64];  // nh in fp16
__device__ unsigned g_odd_or;   // 0 => edge_index is int64 (zero high words)

// ---------- helpers ----------
__device__ __forceinline__ int edge_idx(const void* ei, int table, int e, bool is64) {
    if (is64) return (int)((const long long*)ei)[(size_t)table * EE + e];
    return ((const int*)ei)[(size_t)table * EE + e];
}
__device__ __forceinline__ uint32_t sptr(const void* p) {
    return (uint32_t)__cvta_generic_to_shared(p);
}
__device__ __forceinline__ void ldsm4(uint32_t r[4], uint32_t addr) {
    asm volatile("ldmatrix.sync.aligned.m8n8.x4.shared.b16 {%0,%1,%2,%3}, [%4];"
                 : "=r"(r[0]), "=r"(r[1]), "=r"(r[2]), "=r"(r[3]) : "r"(addr));
}
__device__ __forceinline__ void mma16816(float c[4], const uint32_t a[4],
                                         uint32_t b0, uint32_t b1) {
    asm volatile(
        "mma.sync.aligned.m16n8k16.row.col.f32.f16.f16.f32 "
        "{%0,%1,%2,%3}, {%4,%5,%6,%7}, {%8,%9}, {%0,%1,%2,%3};"
        : "+f"(c[0]), "+f"(c[1]), "+f"(c[2]), "+f"(c[3])
        : "r"(a[0]), "r"(a[1]), "r"(a[2]), "r"(a[3]), "r"(b0), "r"(b1));
}

// ---------- zero counters ----------
__global__ void zero_kernel() {
    int i = blockIdx.x * blockDim.x + threadIdx.x;
    if (i < NN) g_cnt[i] = 0;
    if (i == 0) g_odd_or = 0u;
}

// ---------- detect int32 vs int64 edge_index ----------
__global__ void detect_kernel(const unsigned* __restrict__ ei_words) {
    int t = blockIdx.x * blockDim.x + threadIdx.x;   // 4096 threads
    unsigned v = ei_words[2 * t + 1];
    #pragma unroll
    for (int o = 16; o > 0; o >>= 1) v |= __shfl_xor_sync(0xffffffffu, v, o);
    if ((threadIdx.x & 31) == 0 && v) atomicOr(&g_odd_or, v);
}

// ---------- degree histogram ----------
__global__ void degree_kernel(const void* __restrict__ ei) {
    int e = blockIdx.x * blockDim.x + threadIdx.x;
    if (e >= EE) return;
    bool is64 = (g_odd_or == 0u);
    unsigned dst = (unsigned)edge_idx(ei, 1, e, is64);
    if (dst < NN) atomicAdd(&g_cnt[dst], 1);
}

// ---------- scan pass 1: per-block sums ----------
__global__ void block_sum_kernel() {
    __shared__ int s[256];
    int i = blockIdx.x * 256 + threadIdx.x;
    s[threadIdx.x] = (i < NN) ? g_cnt[i] : 0;
    __syncthreads();
    #pragma unroll
    for (int o = 128; o > 0; o >>= 1) {
        if (threadIdx.x < o) s[threadIdx.x] += s[threadIdx.x + o];
        __syncthreads();
    }
    if (threadIdx.x == 0) g_bsum[blockIdx.x] = s[0];
}

// ---------- scan pass 2: exclusive scan of block sums ----------
__global__ void scan_bsum_kernel() {
    __shared__ int s[512];
    int t = threadIdx.x;
    int v = (t < NBLK) ? g_bsum[t] : 0;
    s[t] = v;
    __syncthreads();
    #pragma unroll
    for (int o = 1; o < 512; o <<= 1) {
        int x = (t >= o) ? s[t - o] : 0;
        __syncthreads();
        s[t] += x;
        __syncthreads();
    }
    if (t < NBLK) g_bscan[t] = s[t] - v;
}

// ---------- scan pass 3: offsets + cursors + dis ----------
__global__ void finalize_kernel() {
    __shared__ int s[256];
    int i = blockIdx.x * 256 + threadIdx.x;
    int v = (i < NN) ? g_cnt[i] : 0;
    s[threadIdx.x] = v;
    __syncthreads();
    #pragma unroll
    for (int o = 1; o < 256; o <<= 1) {
        int x = (threadIdx.x >= o) ? s[threadIdx.x - o] : 0;
        __syncthreads();
        s[threadIdx.x] += x;
        __syncthreads();
    }
    if (i < NN) {
        int off = g_bscan[blockIdx.x] + s[threadIdx.x] - v;
        g_off[i] = off;
        g_cur[i] = off;
        g_dis[i] = (v > 0) ? rsqrtf((float)v) : 0.f;
    }
}

// ---------- bucket fill ----------
__global__ void fill_kernel(const void* __restrict__ ei) {
    int e = blockIdx.x * blockDim.x + threadIdx.x;
    if (e >= EE) return;
    bool is64 = (g_odd_or == 0u);
    int src = edge_idx(ei, 0, e, is64);
    int dst = edge_idx(ei, 1, e, is64);
    if ((unsigned)src >= NN || (unsigned)dst >= NN) return;
    int pos = atomicAdd(&g_cur[dst], 1);
    g_esrc[pos] = src;
}

// ---------- nh -> fp16 ----------
__global__ void nh2h_kernel(const float* __restrict__ nh) {
    int idx = blockIdx.x * blockDim.x + threadIdx.x;
    if (idx < NN * 32) {
        float4 v = __ldg(reinterpret_cast<const float4*>(nh) + idx);
        g_nhh[2 * idx]     = __floats2half2_rn(v.x, v.y);
        g_nhh[2 * idx + 1] = __floats2half2_rn(v.z, v.w);
    }
}

// ---------- fused: aggregate + GEMM1 (relu) + GEMM2 ----------
// Persistent blocks: 256 threads, 2/SM. smem = 128x136 halfs (34.8KB):
// startup: stage W^T fp16 there and extract per-warp A-fragments (held in
// registers for the whole kernel); main loop reuses the same smem as
// SX (x-tile 16x136) and SH (h-tile 16x136).
// mma computes D^T = W^T @ X^T (m=outcols, n=nodes, k=feature).
__global__ void __launch_bounds__(256, 2) fused_kernel(
    const float* __restrict__ W1, const float* __restrict__ b1,
    const float* __restrict__ W2, const float* __restrict__ b2,
    float* __restrict__ out) {
    __shared__ __align__(16) __half smem[128 * 136];
    const int tid = threadIdx.x, lane = tid & 31, warp = tid >> 5;
    const int gid = lane >> 2, tq = lane & 3;
    const int t8 = lane >> 3, tr = lane & 7;

    // ---- stage W (transposed, fp16) and extract A-fragments ----
    uint32_t wf1[8][4], wf2[8][4];
    const int arow = warp * 16 + (t8 & 1) * 8 + tr;   // A-tile rows (outcols)
    #pragma unroll
    for (int which = 0; which < 2; ++which) {
        const float* W = which ? W2 : W1;
        __syncthreads();
        for (int idx = tid; idx < DD * DD; idx += 256) {
            int k = idx >> 7, n = idx & 127;
            smem[n * 136 + k] = __float2half(W[idx]);   // sW[n][k] = W[k][n]
        }
        __syncthreads();
        #pragma unroll
        for (int ks = 0; ks < 8; ++ks) {
            uint32_t a = sptr(&smem[arow * 136 + ks * 16 + (t8 >> 1) * 8]);
            if (which) ldsm4(wf2[ks], a); else ldsm4(wf1[ks], a);
        }
    }
    __syncthreads();
    const float bb10 = __ldg(&b1[warp * 16 + gid]);
    const float bb11 = __ldg(&b1[warp * 16 + gid + 8]);
    const float bb20 = __ldg(&b2[warp * 16 + gid]);
    const float bb21 = __ldg(&b2[warp * 16 + gid + 8]);

    __half* SX = smem;              // [16][136]
    __half* SH = smem + 16 * 136;   // [16][136]

    for (int mt = blockIdx.x; mt < MTILES; mt += gridDim.x) {
        // ---- phase A: aggregate 2 nodes per warp into SX (fp16) ----
        #pragma unroll
        for (int j = 0; j < 2; ++j) {
            int node = mt * 16 + warp * 2 + j;
            int off = g_off[node], len = g_cnt[node];
            float4 acc = make_float4(0.f, 0.f, 0.f, 0.f);
            for (int b = 0; b < len; b += 32) {
                int n = min(32, len - b);
                int src = (lane < n) ? __ldg(&g_esrc[off + b + lane]) : 0;
                float s = (lane < n) ? __ldg(&g_dis[src]) : 0.f;
                for (int i = 0; i < n; ++i) {
                    int   ss = __shfl_sync(0xffffffffu, src, i);
                    float sv = __shfl_sync(0xffffffffu, s, i);
                    float2 raw = __ldg(reinterpret_cast<const float2*>(g_nhh)
                                       + (size_t)ss * 32 + lane);
                    __half2 h0 = *reinterpret_cast<__half2*>(&raw.x);
                    __half2 h1 = *reinterpret_cast<__half2*>(&raw.y);
                    float2 f0 = __half22float2(h0), f1 = __half22float2(h1);
                    acc.x += f0.x * sv; acc.y += f0.y * sv;
                    acc.z += f1.x * sv; acc.w += f1.y * sv;
                }
            }
            float dd = __ldg(&g_dis[node]);
            __half2* p = reinterpret_cast<__half2*>(SX + (warp * 2 + j) * 136 + lane * 4);
            p[0] = __floats2half2_rn(acc.x * dd, acc.y * dd);
            p[1] = __floats2half2_rn(acc.z * dd, acc.w * dd);
        }
        __syncthreads();   // SX ready; also: all prior SH reads finished

        // ---- phase B: GEMM1 (h = relu(x@W1+b1)) -> SH ----
        {
            float c0[4] = {0, 0, 0, 0}, c1[4] = {0, 0, 0, 0};
            #pragma unroll
            for (int ks = 0; ks < 8; ++ks) {
                uint32_t b[4];
                ldsm4(b, sptr(&SX[((t8 >> 1) * 8 + tr) * 136 + ks * 16 + (t8 & 1) * 8]));
                mma16816(c0, wf1[ks], b[0], b[1]);   // nodes 0-7
                mma16816(c1, wf1[ks], b[2], b[3]);   // nodes 8-15
            }
            int oc0 = warp * 16 + gid, oc1 = oc0 + 8;
            int n0 = 2 * tq, n1 = n0 + 1;
            SH[n0 * 136 + oc0] = __float2half(fmaxf(c0[0] + bb10, 0.f));
            SH[n1 * 136 + oc0] = __float2half(fmaxf(c0[1] + bb10, 0.f));
            SH[n0 * 136 + oc1] = __float2half(fmaxf(c0[2] + bb11, 0.f));
            SH[n1 * 136 + oc1] = __float2half(fmaxf(c0[3] + bb11, 0.f));
            SH[(n0 + 8) * 136 + oc0] = __float2half(fmaxf(c1[0] + bb10, 0.f));
            SH[(n1 + 8) * 136 + oc0] = __float2half(fmaxf(c1[1] + bb10, 0.f));
            SH[(n0 + 8) * 136 + oc1] = __float2half(fmaxf(c1[2] + bb11, 0.f));
            SH[(n1 + 8) * 136 + oc1] = __float2half(fmaxf(c1[3] + bb11, 0.f));
        }
        __syncthreads();   // SH ready; SX free for next iteration

        // ---- phase C: GEMM2 (out = h@W2+b2) -> global ----
        {
            float c0[4] = {0, 0, 0, 0}, c1[4] = {0, 0, 0, 0};
            #pragma unroll
            for (int ks = 0; ks < 8; ++ks) {
                uint32_t b[4];
                ldsm4(b, sptr(&SH[((t8 >> 1) * 8 + tr) * 136 + ks * 16 + (t8 & 1) * 8]));
                mma16816(c0, wf2[ks], b[0], b[1]);
                mma16816(c1, wf2[ks], b[2], b[3]);
            }
            int oc0 = warp * 16 + gid, oc1 = oc0 + 8;
            size_t r = (size_t)(mt * 16 + 2 * tq) * DD;
            out[r + oc0]           = c0[0] + bb20;
            out[r + DD + oc0]      = c0[1] + bb20;
            out[r + oc1]           = c0[2] + bb21;
            out[r + DD + oc1]      = c0[3] + bb21;
            size_t r8 = r + (size_t)8 * DD;
            out[r8 + oc0]          = c1[0] + bb20;
            out[r8 + DD + oc0]     = c1[1] + bb20;
            out[r8 + oc1]          = c1[2] + bb21;
            out[r8 + DD + oc1]     = c1[3] + bb21;
        }
    }
}

// ---------- eh passthrough ----------
__global__ void copy_eh_kernel(const float* __restrict__ eh, float* __restrict__ out) {
    int idx = blockIdx.x * blockDim.x + threadIdx.x;
    const int total4 = EE * 16 / 4;
    if (idx < total4)
        reinterpret_cast<float4*>(out)[idx] =
            __ldg(reinterpret_cast<const float4*>(eh) + idx);
}

extern "C" void kernel_launch(void* const* d_in, const int* in_sizes, int n_in,
                              void* d_out, int out_size) {
    const float* nh = nullptr; const float* eh = nullptr; const void* ei = nullptr;
    const float* Wp[2] = {nullptr, nullptr}; const float* bp[2] = {nullptr, nullptr};
    int nw = 0, nb = 0;
    for (int i = 0; i < n_in; ++i) {
        int s = in_sizes[i];
        if (s == NN * DD)            nh = (const float*)d_in[i];
        else if (s == EE * 16)       eh = (const float*)d_in[i];
        else if (s == 2 * EE)        ei = d_in[i];
        else if (s == DD * DD) { if (nw < 2) Wp[nw++] = (const float*)d_in[i]; }
        else if (s == DD)      { if (nb < 2) bp[nb++] = (const float*)d_in[i]; }
    }
    float* out = (float*)d_out;

    zero_kernel<<<NBLK, 256>>>();
    detect_kernel<<<16, 256>>>((const unsigned*)ei);
    degree_kernel<<<(EE + 255) / 256, 256>>>(ei);
    block_sum_kernel<<<NBLK, 256>>>();
    scan_bsum_kernel<<<1, 512>>>();
    finalize_kernel<<<NBLK, 256>>>();
    fill_kernel<<<(EE + 255) / 256, 256>>>(ei);
    nh2h_kernel<<<(NN * 32 + 255) / 256, 256>>>(nh);
    fused_kernel<<<GRID_FUSED, 256>>>(Wp[0], bp[0], Wp[1], bp[1], out);
    copy_eh_kernel<<<(EE * 16 / 4 + 255) / 256, 256>>>(eh, out + (size_t)NN * DD);
}

// round 9
// speedup vs baseline: 1.2552x; 1.2552x over previous
#include <cuda_runtime.h>
#include <cuda_fp16.h>
#include <cstdint>

// GCN layer on GB300, round-9: round-7 split pipeline + fp16 datapath.
//   CSR build -> nh fp16 -> aggregate (warp/node, fp16 gather, fp16 out)
//   -> GEMM1 fp16 HMMA (relu, fp16 out) -> GEMM2 fp16 HMMA (fp32 out)
//   -> eh passthrough.

#define NN 100000
#define EE 1600000
#define DD 128
#define MTILES 6250        // 100000/16
#define NBLK 391           // ceil(NN/256)

__device__ __align__(128) int     g_cnt[NN];
__device__ __align__(128) int     g_off[NN];
__device__ __align__(128) int     g_cur[NN];
__device__ __align__(128) int     g_bsum[512];
__device__ __align__(128) int     g_bscan[512];
__device__ __align__(128) int     g_esrc[EE];
__device__ __align__(128) float   g_dis[NN];
__device__ __align__(128) __half2 g_nhh[(size_t)NN * 64];  // nh fp16
__device__ __align__(128) __half2 g_xh [(size_t)NN * 64];  // agg fp16
__device__ __align__(128) __half2 g_hh [(size_t)NN * 64];  // hidden fp16
__device__ unsigned g_odd_or;   // 0 => edge_index is int64 (zero high words)

// ---------- helpers ----------
__device__ __forceinline__ int edge_idx(const void* ei, int table, int e, bool is64) {
    if (is64) return (int)((const long long*)ei)[(size_t)table * EE + e];
    return ((const int*)ei)[(size_t)table * EE + e];
}
__device__ __forceinline__ uint32_t h2bits(__half2 h) {
    return *reinterpret_cast<uint32_t*>(&h);
}
__device__ __forceinline__ void mma16816(float c[4], const uint32_t a[4],
                                         uint32_t b0, uint32_t b1) {
    asm volatile(
        "mma.sync.aligned.m16n8k16.row.col.f32.f16.f16.f32 "
        "{%0,%1,%2,%3}, {%4,%5,%6,%7}, {%8,%9}, {%0,%1,%2,%3};"
        : "+f"(c[0]), "+f"(c[1]), "+f"(c[2]), "+f"(c[3])
        : "r"(a[0]), "r"(a[1]), "r"(a[2]), "r"(a[3]), "r"(b0), "r"(b1));
}

// ---------- zero counters ----------
__global__ void zero_kernel() {
    int i = blockIdx.x * blockDim.x + threadIdx.x;
    if (i < NN) g_cnt[i] = 0;
    if (i == 0) g_odd_or = 0u;
}

// ---------- detect int32 vs int64 edge_index ----------
__global__ void detect_kernel(const unsigned* __restrict__ ei_words) {
    int t = blockIdx.x * blockDim.x + threadIdx.x;   // 4096 threads
    unsigned v = ei_words[2 * t + 1];
    #pragma unroll
    for (int o = 16; o > 0; o >>= 1) v |= __shfl_xor_sync(0xffffffffu, v, o);
    if ((threadIdx.x & 31) == 0 && v) atomicOr(&g_odd_or, v);
}

// ---------- degree histogram ----------
__global__ void degree_kernel(const void* __restrict__ ei) {
    int e = blockIdx.x * blockDim.x + threadIdx.x;
    if (e >= EE) return;
    bool is64 = (g_odd_or == 0u);
    unsigned dst = (unsigned)edge_idx(ei, 1, e, is64);
    if (dst < NN) atomicAdd(&g_cnt[dst], 1);
}

// ---------- scan pass 1: per-block sums ----------
__global__ void block_sum_kernel() {
    __shared__ int s[256];
    int i = blockIdx.x * 256 + threadIdx.x;
    s[threadIdx.x] = (i < NN) ? g_cnt[i] : 0;
    __syncthreads();
    #pragma unroll
    for (int o = 128; o > 0; o >>= 1) {
        if (threadIdx.x < o) s[threadIdx.x] += s[threadIdx.x + o];
        __syncthreads();
    }
    if (threadIdx.x == 0) g_bsum[blockIdx.x] = s[0];
}

// ---------- scan pass 2: exclusive scan of block sums ----------
__global__ void scan_bsum_kernel() {
    __shared__ int s[512];
    int t = threadIdx.x;
    int v = (t < NBLK) ? g_bsum[t] : 0;
    s[t] = v;
    __syncthreads();
    #pragma unroll
    for (int o = 1; o < 512; o <<= 1) {
        int x = (t >= o) ? s[t - o] : 0;
        __syncthreads();
        s[t] += x;
        __syncthreads();
    }
    if (t < NBLK) g_bscan[t] = s[t] - v;
}

// ---------- scan pass 3: offsets + cursors + dis ----------
__global__ void finalize_kernel() {
    __shared__ int s[256];
    int i = blockIdx.x * 256 + threadIdx.x;
    int v = (i < NN) ? g_cnt[i] : 0;
    s[threadIdx.x] = v;
    __syncthreads();
    #pragma unroll
    for (int o = 1; o < 256; o <<= 1) {
        int x = (threadIdx.x >= o) ? s[threadIdx.x - o] : 0;
        __syncthreads();
        s[threadIdx.x] += x;
        __syncthreads();
    }
    if (i < NN) {
        int off = g_bscan[blockIdx.x] + s[threadIdx.x] - v;
        g_off[i] = off;
        g_cur[i] = off;
        g_dis[i] = (v > 0) ? rsqrtf((float)v) : 0.f;
    }
}

// ---------- bucket fill ----------
__global__ void fill_kernel(const void* __restrict__ ei) {
    int e = blockIdx.x * blockDim.x + threadIdx.x;
    if (e >= EE) return;
    bool is64 = (g_odd_or == 0u);
    int src = edge_idx(ei, 0, e, is64);
    int dst = edge_idx(ei, 1, e, is64);
    if ((unsigned)src >= NN || (unsigned)dst >= NN) return;
    int pos = atomicAdd(&g_cur[dst], 1);
    g_esrc[pos] = src;
}

// ---------- nh -> fp16 ----------
__global__ void nh2h_kernel(const float* __restrict__ nh) {
    int idx = blockIdx.x * blockDim.x + threadIdx.x;
    if (idx < NN * 32) {
        float4 v = __ldg(reinterpret_cast<const float4*>(nh) + idx);
        g_nhh[2 * idx]     = __floats2half2_rn(v.x, v.y);
        g_nhh[2 * idx + 1] = __floats2half2_rn(v.z, v.w);
    }
}

// ---------- aggregate: warp per destination node (fp16 gather) ----------
// g_xh[d] = fp16( (sum nh[src]*dis[src]) * dis[d] ), accumulation in fp32.
__global__ void aggregate_kernel() {
    int w = (blockIdx.x * blockDim.x + threadIdx.x) >> 5;
    int lane = threadIdx.x & 31;
    if (w >= NN) return;
    int off = g_off[w], len = g_cnt[w];
    float4 acc = make_float4(0.f, 0.f, 0.f, 0.f);
    for (int b = 0; b < len; b += 32) {
        int n = min(32, len - b);
        int src = (lane < n) ? __ldg(&g_esrc[off + b + lane]) : 0;
        float s  = (lane < n) ? __ldg(&g_dis[src]) : 0.f;
        for (int i = 0; i < n; ++i) {
            int   ss = __shfl_sync(0xffffffffu, src, i);
            float sv = __shfl_sync(0xffffffffu, s, i);
            float2 raw = __ldg(reinterpret_cast<const float2*>(g_nhh)
                               + (size_t)ss * 32 + lane);
            __half2 h0 = *reinterpret_cast<__half2*>(&raw.x);
            __half2 h1 = *reinterpret_cast<__half2*>(&raw.y);
            float2 f0 = __half22float2(h0), f1 = __half22float2(h1);
            acc.x += f0.x * sv; acc.y += f0.y * sv;
            acc.z += f1.x * sv; acc.w += f1.y * sv;
        }
    }
    float dd = g_dis[w];
    g_xh[(size_t)w * 64 + lane * 2]     = __floats2half2_rn(acc.x * dd, acc.y * dd);
    g_xh[(size_t)w * 64 + lane * 2 + 1] = __floats2half2_rn(acc.z * dd, acc.w * dd);
}

// ---------- GEMM fp16 HMMA m16n8k16: D = X @ W + b ----------
// Block 256 thr (8 warps); warp handles one 16-node m-tile per stride step,
// all 16 n8 tiles. W staged ONCE per block, transposed fp16: sWT[n][k] so
// B-fragment k-pairs are contiguous half2; pad 136 -> conflict-free LDS.
// A-operands: direct half2 global loads (4KB tile, L1-hit across kc loop).
template<bool FIRST>
__global__ void __launch_bounds__(256) gemm_h(
    const float* __restrict__ W, const float* __restrict__ bias,
    float* __restrict__ out) {
    __shared__ __half sWT[128 * 136];
    const int tid = threadIdx.x, lane = tid & 31, warp = tid >> 5;
    const int gid = lane >> 2, tq = lane & 3;

    for (int idx = tid; idx < DD * DD; idx += 256) {
        int k = idx >> 7, n = idx & 127;
        sWT[n * 136 + k] = __float2half(W[idx]);
    }
    __syncthreads();

    const __half2* X = FIRST ? g_xh : g_hh;

    for (int mt = blockIdx.x * 8 + warp; mt < MTILES; mt += gridDim.x * 8) {
        const __half2* X0 = X + (size_t)(mt * 16 + gid) * 64;
        const __half2* X1 = X0 + 8 * 64;

        float acc[16][4];
        #pragma unroll
        for (int t = 0; t < 16; ++t)
            acc[t][0] = acc[t][1] = acc[t][2] = acc[t][3] = 0.f;

        #pragma unroll
        for (int kc = 0; kc < 8; ++kc) {       // k chunks of 16
            uint32_t a[4];
            a[0] = h2bits(__ldg(X0 + kc * 8 + tq));
            a[1] = h2bits(__ldg(X1 + kc * 8 + tq));
            a[2] = h2bits(__ldg(X0 + kc * 8 + 4 + tq));
            a[3] = h2bits(__ldg(X1 + kc * 8 + 4 + tq));
            #pragma unroll
            for (int t = 0; t < 16; ++t) {
                int n = 8 * t + gid;
                uint32_t b0 = h2bits(*reinterpret_cast<const __half2*>(
                    &sWT[n * 136 + kc * 16 + 2 * tq]));
                uint32_t b1 = h2bits(*reinterpret_cast<const __half2*>(
                    &sWT[n * 136 + kc * 16 + 8 + 2 * tq]));
                mma16816(acc[t], a, b0, b1);
            }
        }

        #pragma unroll
        for (int t = 0; t < 16; ++t) {
            int n0 = 8 * t + 2 * tq;
            float2 bb = __ldg(reinterpret_cast<const float2*>(bias + n0));
            float v0 = acc[t][0] + bb.x, v1 = acc[t][1] + bb.y;
            float v2 = acc[t][2] + bb.x, v3 = acc[t][3] + bb.y;
            if (FIRST) {
                g_hh[(size_t)(mt * 16 + gid) * 64 + (n0 >> 1)] =
                    __floats2half2_rn(fmaxf(v0, 0.f), fmaxf(v1, 0.f));
                g_hh[(size_t)(mt * 16 + gid + 8) * 64 + (n0 >> 1)] =
                    __floats2half2_rn(fmaxf(v2, 0.f), fmaxf(v3, 0.f));
            } else {
                size_t r = (size_t)(mt * 16 + gid) * DD;
                *reinterpret_cast<float2*>(out + r + n0) = make_float2(v0, v1);
                *reinterpret_cast<float2*>(out + r + 8 * DD + n0) = make_float2(v2, v3);
            }
        }
    }
}

// ---------- eh passthrough ----------
__global__ void copy_eh_kernel(const float* __restrict__ eh, float* __restrict__ out) {
    int idx = blockIdx.x * blockDim.x + threadIdx.x;
    const int total4 = EE * 16 / 4;
    if (idx < total4)
        reinterpret_cast<float4*>(out)[idx] =
            __ldg(reinterpret_cast<const float4*>(eh) + idx);
}

extern "C" void kernel_launch(void* const* d_in, const int* in_sizes, int n_in,
                              void* d_out, int out_size) {
    const float* nh = nullptr; const float* eh = nullptr; const void* ei = nullptr;
    const float* Wp[2] = {nullptr, nullptr}; const float* bp[2] = {nullptr, nullptr};
    int nw = 0, nb = 0;
    for (int i = 0; i < n_in; ++i) {
        int s = in_sizes[i];
        if (s == NN * DD)            nh = (const float*)d_in[i];
        else if (s == EE * 16)       eh = (const float*)d_in[i];
        else if (s == 2 * EE)        ei = d_in[i];
        else if (s == DD * DD) { if (nw < 2) Wp[nw++] = (const float*)d_in[i]; }
        else if (s == DD)      { if (nb < 2) bp[nb++] = (const float*)d_in[i]; }
    }
    float* out = (float*)d_out;

    zero_kernel<<<NBLK, 256>>>();
    detect_kernel<<<16, 256>>>((const unsigned*)ei);
    degree_kernel<<<(EE + 255) / 256, 256>>>(ei);
    block_sum_kernel<<<NBLK, 256>>>();
    scan_bsum_kernel<<<1, 512>>>();
    finalize_kernel<<<NBLK, 256>>>();
    fill_kernel<<<(EE + 255) / 256, 256>>>(ei);
    nh2h_kernel<<<(NN * 32 + 255) / 256, 256>>>(nh);
    aggregate_kernel<<<(NN * 32 + 255) / 256, 256>>>();
    gemm_h<true ><<<296, 256>>>(Wp[0], bp[0], nullptr);
    gemm_h<false><<<296, 256>>>(Wp[1], bp[1], out);
    copy_eh_kernel<<<(EE * 16 / 4 + 255) / 256, 256>>>(eh, out + (size_t)NN * DD);
}

// round 10
// speedup vs baseline: 1.3955x; 1.1117x over previous
#include <cuda_runtime.h>
#include <cuda_fp16.h>
#include <cstdint>

// GCN layer on GB300, round-10:
//   Stream A: CSR build (zero->detect->degree->scan3->fill) -> aggregate ->
//             fused GEMM1+GEMM2 (register-chained HMMA, h never in memory)
//   Stream B (forked): nh->fp16 convert, eh passthrough copy (overlaps A).

#define NN 100000
#define EE 1600000
#define DD 128
#define MTILES 6250        // 100000/16
#define NBLK 391           // ceil(NN/256)
#define WSTRIDE 136        // padded row for W^T smem
#define SMEM_GEMM (2 * DD * WSTRIDE * (int)sizeof(__half))   // 69,632B

__device__ __align__(128) int     g_cnt[NN];
__device__ __align__(128) int     g_off[NN];
__device__ __align__(128) int     g_cur[NN];
__device__ __align__(128) int     g_bsum[512];
__device__ __align__(128) int     g_bscan[512];
__device__ __align__(128) int     g_esrc[EE];
__device__ __align__(128) float   g_dis[NN];
__device__ __align__(128) __half2 g_nhh[(size_t)NN * 64];  // nh fp16
__device__ __align__(128) __half2 g_xh [(size_t)NN * 64];  // agg fp16
__device__ unsigned g_odd_or;   // 0 => edge_index is int64 (zero high words)

// ---------- helpers ----------
__device__ __forceinline__ int edge_idx(const void* ei, int table, int e, bool is64) {
    if (is64) return (int)((const long long*)ei)[(size_t)table * EE + e];
    return ((const int*)ei)[(size_t)table * EE + e];
}
__device__ __forceinline__ uint32_t h2bits(__half2 h) {
    return *reinterpret_cast<uint32_t*>(&h);
}
__device__ __forceinline__ uint32_t packh2(float a, float b) {
    __half2 h = __floats2half2_rn(a, b);
    return *reinterpret_cast<uint32_t*>(&h);
}
__device__ __forceinline__ void mma16816(float c[4], const uint32_t a[4],
                                         uint32_t b0, uint32_t b1) {
    asm volatile(
        "mma.sync.aligned.m16n8k16.row.col.f32.f16.f16.f32 "
        "{%0,%1,%2,%3}, {%4,%5,%6,%7}, {%8,%9}, {%0,%1,%2,%3};"
        : "+f"(c[0]), "+f"(c[1]), "+f"(c[2]), "+f"(c[3])
        : "r"(a[0]), "r"(a[1]), "r"(a[2]), "r"(a[3]), "r"(b0), "r"(b1));
}

// ---------- zero counters ----------
__global__ void zero_kernel() {
    int i = blockIdx.x * blockDim.x + threadIdx.x;
    if (i < NN) g_cnt[i] = 0;
    if (i == 0) g_odd_or = 0u;
}

// ---------- detect int32 vs int64 edge_index ----------
__global__ void detect_kernel(const unsigned* __restrict__ ei_words) {
    int t = blockIdx.x * blockDim.x + threadIdx.x;   // 4096 threads
    unsigned v = ei_words[2 * t + 1];
    #pragma unroll
    for (int o = 16; o > 0; o >>= 1) v |= __shfl_xor_sync(0xffffffffu, v, o);
    if ((threadIdx.x & 31) == 0 && v) atomicOr(&g_odd_or, v);
}

// ---------- degree histogram ----------
__global__ void degree_kernel(const void* __restrict__ ei) {
    int e = blockIdx.x * blockDim.x + threadIdx.x;
    if (e >= EE) return;
    bool is64 = (g_odd_or == 0u);
    unsigned dst = (unsigned)edge_idx(ei, 1, e, is64);
    if (dst < NN) atomicAdd(&g_cnt[dst], 1);
}

// ---------- scan pass 1: per-block sums ----------
__global__ void block_sum_kernel() {
    __shared__ int s[256];
    int i = blockIdx.x * 256 + threadIdx.x;
    s[threadIdx.x] = (i < NN) ? g_cnt[i] : 0;
    __syncthreads();
    #pragma unroll
    for (int o = 128; o > 0; o >>= 1) {
        if (threadIdx.x < o) s[threadIdx.x] += s[threadIdx.x + o];
        __syncthreads();
    }
    if (threadIdx.x == 0) g_bsum[blockIdx.x] = s[0];
}

// ---------- scan pass 2: exclusive scan of block sums ----------
__global__ void scan_bsum_kernel() {
    __shared__ int s[512];
    int t = threadIdx.x;
    int v = (t < NBLK) ? g_bsum[t] : 0;
    s[t] = v;
    __syncthreads();
    #pragma unroll
    for (int o = 1; o < 512; o <<= 1) {
        int x = (t >= o) ? s[t - o] : 0;
        __syncthreads();
        s[t] += x;
        __syncthreads();
    }
    if (t < NBLK) g_bscan[t] = s[t] - v;
}

// ---------- scan pass 3: offsets + cursors + dis ----------
__global__ void finalize_kernel() {
    __shared__ int s[256];
    int i = blockIdx.x * 256 + threadIdx.x;
    int v = (i < NN) ? g_cnt[i] : 0;
    s[threadIdx.x] = v;
    __syncthreads();
    #pragma unroll
    for (int o = 1; o < 256; o <<= 1) {
        int x = (threadIdx.x >= o) ? s[threadIdx.x - o] : 0;
        __syncthreads();
        s[threadIdx.x] += x;
        __syncthreads();
    }
    if (i < NN) {
        int off = g_bscan[blockIdx.x] + s[threadIdx.x] - v;
        g_off[i] = off;
        g_cur[i] = off;
        g_dis[i] = (v > 0) ? rsqrtf((float)v) : 0.f;
    }
}

// ---------- bucket fill ----------
__global__ void fill_kernel(const void* __restrict__ ei) {
    int e = blockIdx.x * blockDim.x + threadIdx.x;
    if (e >= EE) return;
    bool is64 = (g_odd_or == 0u);
    int src = edge_idx(ei, 0, e, is64);
    int dst = edge_idx(ei, 1, e, is64);
    if ((unsigned)src >= NN || (unsigned)dst >= NN) return;
    int pos = atomicAdd(&g_cur[dst], 1);
    g_esrc[pos] = src;
}

// ---------- nh -> fp16 (stream B) ----------
__global__ void nh2h_kernel(const float* __restrict__ nh) {
    int idx = blockIdx.x * blockDim.x + threadIdx.x;
    if (idx < NN * 32) {
        float4 v = __ldg(reinterpret_cast<const float4*>(nh) + idx);
        g_nhh[2 * idx]     = __floats2half2_rn(v.x, v.y);
        g_nhh[2 * idx + 1] = __floats2half2_rn(v.z, v.w);
    }
}

// ---------- aggregate: warp per destination node (fp16 gather) ----------
__global__ void aggregate_kernel() {
    int w = (blockIdx.x * blockDim.x + threadIdx.x) >> 5;
    int lane = threadIdx.x & 31;
    if (w >= NN) return;
    int off = g_off[w], len = g_cnt[w];
    float4 acc = make_float4(0.f, 0.f, 0.f, 0.f);
    for (int b = 0; b < len; b += 32) {
        int n = min(32, len - b);
        int src = (lane < n) ? __ldg(&g_esrc[off + b + lane]) : 0;
        float s  = (lane < n) ? __ldg(&g_dis[src]) : 0.f;
        for (int i = 0; i < n; ++i) {
            int   ss = __shfl_sync(0xffffffffu, src, i);
            float sv = __shfl_sync(0xffffffffu, s, i);
            float2 raw = __ldg(reinterpret_cast<const float2*>(g_nhh)
                               + (size_t)ss * 32 + lane);
            __half2 h0 = *reinterpret_cast<__half2*>(&raw.x);
            __half2 h1 = *reinterpret_cast<__half2*>(&raw.y);
            float2 f0 = __half22float2(h0), f1 = __half22float2(h1);
            acc.x += f0.x * sv; acc.y += f0.y * sv;
            acc.z += f1.x * sv; acc.w += f1.y * sv;
        }
    }
    float dd = g_dis[w];
    g_xh[(size_t)w * 64 + lane * 2]     = __floats2half2_rn(acc.x * dd, acc.y * dd);
    g_xh[(size_t)w * 64 + lane * 2 + 1] = __floats2half2_rn(acc.z * dd, acc.w * dd);
}

// ---------- fused GEMM1+GEMM2, register-chained HMMA ----------
// out = relu(x@W1+b1)@W2 + b2. Key: mma acc layout (c0,c1=row gid,
// c2,c3=row gid+8 at cols 2tq,2tq+1) IS the A-frag layout of the next mma
// (a0..a3 at k=16kc+2tq / +8) -> h stays in registers. W1^T/W2^T in
// dynamic smem (pad 136), staged once per block.
__global__ void __launch_bounds__(256) gemm12_kernel(
    const float* __restrict__ W1, const float* __restrict__ b1,
    const float* __restrict__ W2, const float* __restrict__ b2,
    float* __restrict__ out) {
    extern __shared__ __half sW[];
    __half* sW1 = sW;
    __half* sW2 = sW + DD * WSTRIDE;
    const int tid = threadIdx.x, lane = tid & 31, warp = tid >> 5;
    const int gid = lane >> 2, tq = lane & 3;

    for (int idx = tid; idx < DD * DD; idx += 256) {
        int k = idx >> 7, n = idx & 127;
        sW1[n * WSTRIDE + k] = __float2half(W1[idx]);
        sW2[n * WSTRIDE + k] = __float2half(W2[idx]);
    }
    __syncthreads();

    for (int mt = blockIdx.x * 8 + warp; mt < MTILES; mt += gridDim.x * 8) {
        const __half2* X0 = g_xh + (size_t)(mt * 16 + gid) * 64;
        const __half2* X1 = X0 + 8 * 64;

        // ---- GEMM1: acc1 = x @ W1 ----
        float acc1[16][4];
        #pragma unroll
        for (int t = 0; t < 16; ++t)
            acc1[t][0] = acc1[t][1] = acc1[t][2] = acc1[t][3] = 0.f;
        #pragma unroll
        for (int kc = 0; kc < 8; ++kc) {
            uint32_t a[4];
            a[0] = h2bits(__ldg(X0 + kc * 8 + tq));
            a[1] = h2bits(__ldg(X1 + kc * 8 + tq));
            a[2] = h2bits(__ldg(X0 + kc * 8 + 4 + tq));
            a[3] = h2bits(__ldg(X1 + kc * 8 + 4 + tq));
            #pragma unroll
            for (int t = 0; t < 16; ++t) {
                int n = 8 * t + gid;
                uint32_t b0 = h2bits(*reinterpret_cast<const __half2*>(
                    &sW1[n * WSTRIDE + kc * 16 + 2 * tq]));
                uint32_t b1v = h2bits(*reinterpret_cast<const __half2*>(
                    &sW1[n * WSTRIDE + kc * 16 + 8 + 2 * tq]));
                mma16816(acc1[t], a, b0, b1v);
            }
        }

        // ---- GEMM2: acc2 = relu(acc1+b1) @ W2, h via register repack ----
        float acc2[16][4];
        #pragma unroll
        for (int t = 0; t < 16; ++t)
            acc2[t][0] = acc2[t][1] = acc2[t][2] = acc2[t][3] = 0.f;
        #pragma unroll
        for (int kc = 0; kc < 8; ++kc) {
            int t0 = 2 * kc, t1 = 2 * kc + 1;
            float2 bbA = __ldg(reinterpret_cast<const float2*>(b1 + 8 * t0 + 2 * tq));
            float2 bbB = __ldg(reinterpret_cast<const float2*>(b1 + 8 * t1 + 2 * tq));
            uint32_t ha[4];
            ha[0] = packh2(fmaxf(acc1[t0][0] + bbA.x, 0.f),
                           fmaxf(acc1[t0][1] + bbA.y, 0.f));
            ha[1] = packh2(fmaxf(acc1[t0][2] + bbA.x, 0.f),
                           fmaxf(acc1[t0][3] + bbA.y, 0.f));
            ha[2] = packh2(fmaxf(acc1[t1][0] + bbB.x, 0.f),
                           fmaxf(acc1[t1][1] + bbB.y, 0.f));
            ha[3] = packh2(fmaxf(acc1[t1][2] + bbB.x, 0.f),
                           fmaxf(acc1[t1][3] + bbB.y, 0.f));
            #pragma unroll
            for (int t = 0; t < 16; ++t) {
                int n = 8 * t + gid;
                uint32_t b0 = h2bits(*reinterpret_cast<const __half2*>(
                    &sW2[n * WSTRIDE + kc * 16 + 2 * tq]));
                uint32_t b1v = h2bits(*reinterpret_cast<const __half2*>(
                    &sW2[n * WSTRIDE + kc * 16 + 8 + 2 * tq]));
                mma16816(acc2[t], ha, b0, b1v);
            }
        }

        // ---- epilogue: + b2 -> out ----
        size_t r0 = (size_t)(mt * 16 + gid) * DD;
        size_t r1 = r0 + (size_t)8 * DD;
        #pragma unroll
        for (int t = 0; t < 16; ++t) {
            int n0 = 8 * t + 2 * tq;
            float2 bb = __ldg(reinterpret_cast<const float2*>(b2 + n0));
            *reinterpret_cast<float2*>(out + r0 + n0) =
                make_float2(acc2[t][0] + bb.x, acc2[t][1] + bb.y);
            *reinterpret_cast<float2*>(out + r1 + n0) =
                make_float2(acc2[t][2] + bb.x, acc2[t][3] + bb.y);
        }
    }
}

// ---------- eh passthrough (stream B) ----------
__global__ void copy_eh_kernel(const float* __restrict__ eh, float* __restrict__ out) {
    int idx = blockIdx.x * blockDim.x + threadIdx.x;
    const int total4 = EE * 16 / 4;
    if (idx < total4)
        reinterpret_cast<float4*>(out)[idx] =
            __ldg(reinterpret_cast<const float4*>(eh) + idx);
}

extern "C" void kernel_launch(void* const* d_in, const int* in_sizes, int n_in,
                              void* d_out, int out_size) {
    const float* nh = nullptr; const float* eh = nullptr; const void* ei = nullptr;
    const float* Wp[2] = {nullptr, nullptr}; const float* bp[2] = {nullptr, nullptr};
    int nw = 0, nb = 0;
    for (int i = 0; i < n_in; ++i) {
        int s = in_sizes[i];
        if (s == NN * DD)            nh = (const float*)d_in[i];
        else if (s == EE * 16)       eh = (const float*)d_in[i];
        else if (s == 2 * EE)        ei = d_in[i];
        else if (s == DD * DD) { if (nw < 2) Wp[nw++] = (const float*)d_in[i]; }
        else if (s == DD)      { if (nb < 2) bp[nb++] = (const float*)d_in[i]; }
    }
    float* out = (float*)d_out;

    // Lazy one-time setup (runs on the uncaptured correctness call; reused
    // inside capture afterwards). No device memory is allocated.
    static cudaStream_t sB = nullptr;
    static cudaEvent_t evFork = nullptr, evNh = nullptr, evEh = nullptr;
    static bool attrSet = false;
    if (!sB) {
        cudaStreamCreateWithFlags(&sB, cudaStreamNonBlocking);
        cudaEventCreateWithFlags(&evFork, cudaEventDisableTiming);
        cudaEventCreateWithFlags(&evNh,   cudaEventDisableTiming);
        cudaEventCreateWithFlags(&evEh,   cudaEventDisableTiming);
    }
    if (!attrSet) {
        cudaFuncSetAttribute(gemm12_kernel,
                             cudaFuncAttributeMaxDynamicSharedMemorySize, SMEM_GEMM);
        attrSet = true;
    }

    // ---- fork stream B: nh->fp16, eh copy (independent of CSR chain) ----
    cudaEventRecord(evFork, 0);
    cudaStreamWaitEvent(sB, evFork, 0);
    nh2h_kernel<<<(NN * 32 + 255) / 256, 256, 0, sB>>>(nh);
    cudaEventRecord(evNh, sB);
    copy_eh_kernel<<<(EE * 16 / 4 + 255) / 256, 256, 0, sB>>>(
        eh, out + (size_t)NN * DD);
    cudaEventRecord(evEh, sB);

    // ---- stream A: CSR build ----
    zero_kernel<<<NBLK, 256>>>();
    detect_kernel<<<16, 256>>>((const unsigned*)ei);
    degree_kernel<<<(EE + 255) / 256, 256>>>(ei);
    block_sum_kernel<<<NBLK, 256>>>();
    scan_bsum_kernel<<<1, 512>>>();
    finalize_kernel<<<NBLK, 256>>>();
    fill_kernel<<<(EE + 255) / 256, 256>>>(ei);

    // aggregate needs nh2h done
    cudaStreamWaitEvent(0, evNh, 0);
    aggregate_kernel<<<(NN * 32 + 255) / 256, 256>>>();
    gemm12_kernel<<<296, 256, SMEM_GEMM>>>(Wp[0], bp[0], Wp[1], bp[1], out);

    // join stream B before returning to harness
    cudaStreamWaitEvent(0, evEh, 0);
}

// round 11
// speedup vs baseline: 1.4201x; 1.0176x over previous
#include <cuda_runtime.h>
#include <cuda_fp16.h>
#include <cstdint>

// GCN layer on GB300, round-11: launch-count reduction.
//   Stream A: init(+dtype detect) -> degree -> single-pass lookback scan
//             (offsets+cursors+dis) -> fill -> aggregate -> fused GEMM1+2.
//   Stream B (forked): nh->fp16, eh passthrough (overlaps A).

#define NN 100000
#define EE 1600000
#define DD 128
#define MTILES 6250        // 100000/16
#define NBLK 391           // ceil(NN/256)
#define WSTRIDE 136        // padded row for W^T smem
#define SMEM_GEMM (2 * DD * WSTRIDE * (int)sizeof(__half))   // 69,632B

__device__ __align__(128) int     g_cnt[NN];
__device__ __align__(128) int     g_off[NN];
__device__ __align__(128) int     g_cur[NN];
__device__ __align__(128) unsigned long long g_comb[NBLK];  // scan state
__device__ __align__(128) int     g_esrc[EE];
__device__ __align__(128) float   g_dis[NN];
__device__ __align__(128) __half2 g_nhh[(size_t)NN * 64];  // nh fp16
__device__ __align__(128) __half2 g_xh [(size_t)NN * 64];  // agg fp16
__device__ unsigned g_odd_or;   // 0 => edge_index is int64 (zero high words)

// ---------- helpers ----------
__device__ __forceinline__ int edge_idx(const void* ei, int table, int e, bool is64) {
    if (is64) return (int)((const long long*)ei)[(size_t)table * EE + e];
    return ((const int*)ei)[(size_t)table * EE + e];
}
__device__ __forceinline__ uint32_t h2bits(__half2 h) {
    return *reinterpret_cast<uint32_t*>(&h);
}
__device__ __forceinline__ uint32_t packh2(float a, float b) {
    __half2 h = __floats2half2_rn(a, b);
    return *reinterpret_cast<uint32_t*>(&h);
}
__device__ __forceinline__ void mma16816(float c[4], const uint32_t a[4],
                                         uint32_t b0, uint32_t b1) {
    asm volatile(
        "mma.sync.aligned.m16n8k16.row.col.f32.f16.f16.f32 "
        "{%0,%1,%2,%3}, {%4,%5,%6,%7}, {%8,%9}, {%0,%1,%2,%3};"
        : "+f"(c[0]), "+f"(c[1]), "+f"(c[2]), "+f"(c[3])
        : "r"(a[0]), "r"(a[1]), "r"(a[2]), "r"(a[3]), "r"(b0), "r"(b1));
}

// ---------- init: zero counters + scan state, block 0 detects idx dtype ----
__global__ void init_kernel(const unsigned* __restrict__ ei_words) {
    int i = blockIdx.x * 256 + threadIdx.x;
    if (i < NN) g_cnt[i] = 0;
    if (i < NBLK) g_comb[i] = 0ull;
    if (blockIdx.x == 0) {
        // int64 (values < 2^31): odd 32-bit words all zero over 4096 samples.
        __shared__ unsigned sred[256];
        unsigned v = 0;
        #pragma unroll
        for (int j = 0; j < 16; ++j)
            v |= ei_words[2 * (threadIdx.x + 256 * j) + 1];
        sred[threadIdx.x] = v;
        __syncthreads();
        #pragma unroll
        for (int o = 128; o > 0; o >>= 1) {
            if (threadIdx.x < o) sred[threadIdx.x] |= sred[threadIdx.x + o];
            __syncthreads();
        }
        if (threadIdx.x == 0) g_odd_or = sred[0];   // plain store, deterministic
    }
}

// ---------- degree histogram ----------
__global__ void degree_kernel(const void* __restrict__ ei) {
    int e = blockIdx.x * blockDim.x + threadIdx.x;
    if (e >= EE) return;
    bool is64 = (g_odd_or == 0u);
    unsigned dst = (unsigned)edge_idx(ei, 1, e, is64);
    if (dst < NN) atomicAdd(&g_cnt[dst], 1);
}

// ---------- single-pass scan (decoupled lookback) ----------
// 391 blocks, ALL simultaneously resident (1184 slots) -> spins are safe.
// g_comb[b] packs (status<<32)|value: 1=aggregate ready, 2=prefix ready.
// Emits exclusive offsets, fill cursors and dis in the same kernel.
__global__ void __launch_bounds__(256) scan_kernel() {
    __shared__ int s[256];
    __shared__ int sprefix;
    const int tid = threadIdx.x, b = blockIdx.x;
    int i = b * 256 + tid;
    int v = (i < NN) ? g_cnt[i] : 0;
    s[tid] = v;
    __syncthreads();
    #pragma unroll
    for (int o = 1; o < 256; o <<= 1) {
        int x = (tid >= o) ? s[tid - o] : 0;
        __syncthreads();
        s[tid] += x;
        __syncthreads();
    }
    int agg = s[255];
    if (tid == 0) {
        if (b == 0) {
            sprefix = 0;
            atomicExch(&g_comb[0], (2ull << 32) | (unsigned)agg);
        } else {
            atomicExch(&g_comb[b], (1ull << 32) | (unsigned)agg);
        }
    }
    if (b > 0 && tid < 32) {
        const int lane = tid;
        int prefix = 0;
        int base = b - 1;
        while (true) {
            int idx = base - lane;
            unsigned long long c;
            unsigned st;
            do {
                c = (idx >= 0) ? atomicAdd(&g_comb[idx], 0ull) : (2ull << 32);
                st = (unsigned)(c >> 32);
            } while (__any_sync(0xffffffffu, st == 0));
            int val = (int)(c & 0xffffffffu);
            unsigned m2 = __ballot_sync(0xffffffffu, st == 2);
            if (m2) {
                int firstp = __ffs(m2) - 1;   // nearest prefix-ready block
                int contrib = (lane <= firstp) ? val : 0;
                prefix += __reduce_add_sync(0xffffffffu, contrib);
                break;
            }
            prefix += __reduce_add_sync(0xffffffffu, val);
            base -= 32;
        }
        if (lane == 0) {
            atomicExch(&g_comb[b], (2ull << 32) | (unsigned)(prefix + agg));
            sprefix = prefix;
        }
    }
    __syncthreads();
    if (i < NN) {
        int excl = sprefix + s[tid] - v;
        g_off[i] = excl;
        g_cur[i] = excl;
        g_dis[i] = (v > 0) ? rsqrtf((float)v) : 0.f;
    }
}

// ---------- bucket fill ----------
__global__ void fill_kernel(const void* __restrict__ ei) {
    int e = blockIdx.x * blockDim.x + threadIdx.x;
    if (e >= EE) return;
    bool is64 = (g_odd_or == 0u);
    int src = edge_idx(ei, 0, e, is64);
    int dst = edge_idx(ei, 1, e, is64);
    if ((unsigned)src >= NN || (unsigned)dst >= NN) return;
    int pos = atomicAdd(&g_cur[dst], 1);
    g_esrc[pos] = src;
}

// ---------- nh -> fp16 (stream B) ----------
__global__ void nh2h_kernel(const float* __restrict__ nh) {
    int idx = blockIdx.x * blockDim.x + threadIdx.x;
    if (idx < NN * 32) {
        float4 v = __ldg(reinterpret_cast<const float4*>(nh) + idx);
        g_nhh[2 * idx]     = __floats2half2_rn(v.x, v.y);
        g_nhh[2 * idx + 1] = __floats2half2_rn(v.z, v.w);
    }
}

// ---------- aggregate: warp per destination node (fp16 gather) ----------
__global__ void aggregate_kernel() {
    int w = (blockIdx.x * blockDim.x + threadIdx.x) >> 5;
    int lane = threadIdx.x & 31;
    if (w >= NN) return;
    int off = g_off[w], len = g_cnt[w];
    float4 acc = make_float4(0.f, 0.f, 0.f, 0.f);
    for (int b = 0; b < len; b += 32) {
        int n = min(32, len - b);
        int src = (lane < n) ? __ldg(&g_esrc[off + b + lane]) : 0;
        float s  = (lane < n) ? __ldg(&g_dis[src]) : 0.f;
        for (int i = 0; i < n; ++i) {
            int   ss = __shfl_sync(0xffffffffu, src, i);
            float sv = __shfl_sync(0xffffffffu, s, i);
            float2 raw = __ldg(reinterpret_cast<const float2*>(g_nhh)
                               + (size_t)ss * 32 + lane);
            __half2 h0 = *reinterpret_cast<__half2*>(&raw.x);
            __half2 h1 = *reinterpret_cast<__half2*>(&raw.y);
            float2 f0 = __half22float2(h0), f1 = __half22float2(h1);
            acc.x += f0.x * sv; acc.y += f0.y * sv;
            acc.z += f1.x * sv; acc.w += f1.y * sv;
        }
    }
    float dd = g_dis[w];
    g_xh[(size_t)w * 64 + lane * 2]     = __floats2half2_rn(acc.x * dd, acc.y * dd);
    g_xh[(size_t)w * 64 + lane * 2 + 1] = __floats2half2_rn(acc.z * dd, acc.w * dd);
}

// ---------- fused GEMM1+GEMM2, register-chained HMMA ----------
// out = relu(x@W1+b1)@W2 + b2; h never leaves registers (mma acc layout
// == next mma's A-frag layout). W1^T/W2^T staged once in dynamic smem.
__global__ void __launch_bounds__(256) gemm12_kernel(
    const float* __restrict__ W1, const float* __restrict__ b1,
    const float* __restrict__ W2, const float* __restrict__ b2,
    float* __restrict__ out) {
    extern __shared__ __half sW[];
    __half* sW1 = sW;
    __half* sW2 = sW + DD * WSTRIDE;
    const int tid = threadIdx.x, lane = tid & 31, warp = tid >> 5;
    const int gid = lane >> 2, tq = lane & 3;

    for (int idx = tid; idx < DD * DD; idx += 256) {
        int k = idx >> 7, n = idx & 127;
        sW1[n * WSTRIDE + k] = __float2half(W1[idx]);
        sW2[n * WSTRIDE + k] = __float2half(W2[idx]);
    }
    __syncthreads();

    for (int mt = blockIdx.x * 8 + warp; mt < MTILES; mt += gridDim.x * 8) {
        const __half2* X0 = g_xh + (size_t)(mt * 16 + gid) * 64;
        const __half2* X1 = X0 + 8 * 64;

        float acc1[16][4];
        #pragma unroll
        for (int t = 0; t < 16; ++t)
            acc1[t][0] = acc1[t][1] = acc1[t][2] = acc1[t][3] = 0.f;
        #pragma unroll
        for (int kc = 0; kc < 8; ++kc) {
            uint32_t a[4];
            a[0] = h2bits(__ldg(X0 + kc * 8 + tq));
            a[1] = h2bits(__ldg(X1 + kc * 8 + tq));
            a[2] = h2bits(__ldg(X0 + kc * 8 + 4 + tq));
            a[3] = h2bits(__ldg(X1 + kc * 8 + 4 + tq));
            #pragma unroll
            for (int t = 0; t < 16; ++t) {
                int n = 8 * t + gid;
                uint32_t b0 = h2bits(*reinterpret_cast<const __half2*>(
                    &sW1[n * WSTRIDE + kc * 16 + 2 * tq]));
                uint32_t b1v = h2bits(*reinterpret_cast<const __half2*>(
                    &sW1[n * WSTRIDE + kc * 16 + 8 + 2 * tq]));
                mma16816(acc1[t], a, b0, b1v);
            }
        }

        float acc2[16][4];
        #pragma unroll
        for (int t = 0; t < 16; ++t)
            acc2[t][0] = acc2[t][1] = acc2[t][2] = acc2[t][3] = 0.f;
        #pragma unroll
        for (int kc = 0; kc < 8; ++kc) {
            int t0 = 2 * kc, t1 = 2 * kc + 1;
            float2 bbA = __ldg(reinterpret_cast<const float2*>(b1 + 8 * t0 + 2 * tq));
            float2 bbB = __ldg(reinterpret_cast<const float2*>(b1 + 8 * t1 + 2 * tq));
            uint32_t ha[4];
            ha[0] = packh2(fmaxf(acc1[t0][0] + bbA.x, 0.f),
                           fmaxf(acc1[t0][1] + bbA.y, 0.f));
            ha[1] = packh2(fmaxf(acc1[t0][2] + bbA.x, 0.f),
                           fmaxf(acc1[t0][3] + bbA.y, 0.f));
            ha[2] = packh2(fmaxf(acc1[t1][0] + bbB.x, 0.f),
                           fmaxf(acc1[t1][1] + bbB.y, 0.f));
            ha[3] = packh2(fmaxf(acc1[t1][2] + bbB.x, 0.f),
                           fmaxf(acc1[t1][3] + bbB.y, 0.f));
            #pragma unroll
            for (int t = 0; t < 16; ++t) {
                int n = 8 * t + gid;
                uint32_t b0 = h2bits(*reinterpret_cast<const __half2*>(
                    &sW2[n * WSTRIDE + kc * 16 + 2 * tq]));
                uint32_t b1v = h2bits(*reinterpret_cast<const __half2*>(
                    &sW2[n * WSTRIDE + kc * 16 + 8 + 2 * tq]));
                mma16816(acc2[t], ha, b0, b1v);
            }
        }

        size_t r0 = (size_t)(mt * 16 + gid) * DD;
        size_t r1 = r0 + (size_t)8 * DD;
        #pragma unroll
        for (int t = 0; t < 16; ++t) {
            int n0 = 8 * t + 2 * tq;
            float2 bb = __ldg(reinterpret_cast<const float2*>(b2 + n0));
            *reinterpret_cast<float2*>(out + r0 + n0) =
                make_float2(acc2[t][0] + bb.x, acc2[t][1] + bb.y);
            *reinterpret_cast<float2*>(out + r1 + n0) =
                make_float2(acc2[t][2] + bb.x, acc2[t][3] + bb.y);
        }
    }
}

// ---------- eh passthrough (stream B) ----------
__global__ void copy_eh_kernel(const float* __restrict__ eh, float* __restrict__ out) {
    int idx = blockIdx.x * blockDim.x + threadIdx.x;
    const int total4 = EE * 16 / 4;
    if (idx < total4)
        reinterpret_cast<float4*>(out)[idx] =
            __ldg(reinterpret_cast<const float4*>(eh) + idx);
}

extern "C" void kernel_launch(void* const* d_in, const int* in_sizes, int n_in,
                              void* d_out, int out_size) {
    const float* nh = nullptr; const float* eh = nullptr; const void* ei = nullptr;
    const float* Wp[2] = {nullptr, nullptr}; const float* bp[2] = {nullptr, nullptr};
    int nw = 0, nb = 0;
    for (int i = 0; i < n_in; ++i) {
        int s = in_sizes[i];
        if (s == NN * DD)            nh = (const float*)d_in[i];
        else if (s == EE * 16)       eh = (const float*)d_in[i];
        else if (s == 2 * EE)        ei = d_in[i];
        else if (s == DD * DD) { if (nw < 2) Wp[nw++] = (const float*)d_in[i]; }
        else if (s == DD)      { if (nb < 2) bp[nb++] = (const float*)d_in[i]; }
    }
    float* out = (float*)d_out;

    // Lazy one-time setup (first call is uncaptured; reused inside capture).
    static cudaStream_t sB = nullptr;
    static cudaEvent_t evFork = nullptr, evNh = nullptr, evEh = nullptr;
    static bool attrSet = false;
    if (!sB) {
        cudaStreamCreateWithFlags(&sB, cudaStreamNonBlocking);
        cudaEventCreateWithFlags(&evFork, cudaEventDisableTiming);
        cudaEventCreateWithFlags(&evNh,   cudaEventDisableTiming);
        cudaEventCreateWithFlags(&evEh,   cudaEventDisableTiming);
    }
    if (!attrSet) {
        cudaFuncSetAttribute(gemm12_kernel,
                             cudaFuncAttributeMaxDynamicSharedMemorySize, SMEM_GEMM);
        attrSet = true;
    }

    // ---- fork stream B: nh->fp16, eh copy ----
    cudaEventRecord(evFork, 0);
    cudaStreamWaitEvent(sB, evFork, 0);
    nh2h_kernel<<<(NN * 32 + 255) / 256, 256, 0, sB>>>(nh);
    cudaEventRecord(evNh, sB);
    copy_eh_kernel<<<(EE * 16 / 4 + 255) / 256, 256, 0, sB>>>(
        eh, out + (size_t)NN * DD);
    cudaEventRecord(evEh, sB);

    // ---- stream A: CSR build (3 launches) ----
    init_kernel<<<NBLK, 256>>>((const unsigned*)ei);
    degree_kernel<<<(EE + 255) / 256, 256>>>(ei);
    scan_kernel<<<NBLK, 256>>>();
    fill_kernel<<<(EE + 255) / 256, 256>>>(ei);

    // aggregate needs nh2h done
    cudaStreamWaitEvent(0, evNh, 0);
    aggregate_kernel<<<(NN * 32 + 255) / 256, 256>>>();
    gemm12_kernel<<<296, 256, SMEM_GEMM>>>(Wp[0], bp[0], Wp[1], bp[1], out);

    // join stream B
    cudaStreamWaitEvent(0, evEh, 0);
}